// round 1
// baseline (speedup 1.0000x reference)
#include <cuda_runtime.h>
#include <cuda_bf16.h>

// Problem constants (fixed by the dataset)
#define NT 4            // B*C trees
#define NN 262144       // nodes per tree (2^18)
#define NPIX (1024*1024)
#define TOTN (NT*NN)            // 1,048,576 nodes total
#define TOTP (NT*NPIX)          // 4,194,304 pixels total

// Scratch: packed (parent, c) jump tables (ping-pong) and per-node values.
// int2.x = jump-parent index (0 = root reached), int2.y = bit-pattern of float partial sum
__device__ int2  g_bufA[TOTN];
__device__ int2  g_bufB[TOTN];
__device__ float g_v[TOTN];

// ---------------------------------------------------------------------------
// K1: c[i] = sigmoid(clamp(1000*(attr-thr),-12,12)) * (levels[i]-levels[parent[i]])
//     c[0] = levels[0]; pack (parent, c) into g_bufA.
// ---------------------------------------------------------------------------
__global__ void k_build(const float* __restrict__ attr,
                        const float* __restrict__ levels,
                        const float* __restrict__ thr,
                        const int*   __restrict__ parent)
{
    int idx = blockIdx.x * blockDim.x + threadIdx.x;
    if (idx >= TOTN) return;
    int i = idx & (NN - 1);
    int base = idx & ~(NN - 1);

    float lv = levels[idx];
    int p;
    float c;
    if (i == 0) {
        p = 0;
        c = lv;                      // c[0] = levels[0]
    } else {
        p = parent[idx];
        float lp = __ldg(&levels[base + p]);
        float z = 1000.0f * (attr[idx] - thr[0]);
        z = fminf(fmaxf(z, -12.0f), 12.0f);
        float s = 1.0f / (1.0f + __expf(-z));
        c = s * (lv - lp);
    }
    g_bufA[idx] = make_int2(p, __float_as_int(c));
}

// ---------------------------------------------------------------------------
// K2..K4: jump doubling. out[i] = (p2, c + c[p]) with zero-fill at root:
// when p==0 the chain has terminated (root's own c is added separately at climb).
// ---------------------------------------------------------------------------
__global__ void k_double(const int2* __restrict__ in, int2* __restrict__ out)
{
    int idx = blockIdx.x * blockDim.x + threadIdx.x;
    if (idx >= TOTN) return;
    int base = idx & ~(NN - 1);

    int2 a = in[idx];
    if (a.x != 0) {
        int2 b = __ldg(&in[base + a.x]);
        a.y = __float_as_int(__int_as_float(a.y) + __int_as_float(b.y));
        a.x = b.x;
    }
    out[idx] = a;
}

// ---------------------------------------------------------------------------
// K5: per-node climb using the jump-8 table. v[i] = c[0] + sum of jump sums.
// Mean ~2 steps/node (depth ~12.5, jump 8); hot low-index head stays in L1/L2.
// ---------------------------------------------------------------------------
__global__ void k_climb(const int2* __restrict__ jp)
{
    int idx = blockIdx.x * blockDim.x + threadIdx.x;
    if (idx >= TOTN) return;
    int base = idx & ~(NN - 1);

    float acc = __int_as_float(__ldg(&jp[base].y));   // c[0] = levels[0]
    int j = idx & (NN - 1);
    while (j != 0) {
        int2 a = __ldg(&jp[base + j]);
        acc += __int_as_float(a.y);
        j = a.x;
    }
    g_v[idx] = acc;
}

// ---------------------------------------------------------------------------
// K6: y[p] = v[tree(p)*NN + pixel_to_node[p]], 4 pixels per thread (int4/float4)
// ---------------------------------------------------------------------------
__global__ void k_gather(const int* __restrict__ ptn, float* __restrict__ y)
{
    int q = blockIdx.x * blockDim.x + threadIdx.x;   // quad index
    if (q >= TOTP / 4) return;
    int p0 = q * 4;
    int base = (p0 >> 20) << 18;                     // tree * NN  (NPIX = 2^20)

    int4 n = __ldg(reinterpret_cast<const int4*>(ptn) + q);
    float4 o;
    o.x = __ldg(&g_v[base + n.x]);
    o.y = __ldg(&g_v[base + n.y]);
    o.z = __ldg(&g_v[base + n.z]);
    o.w = __ldg(&g_v[base + n.w]);
    reinterpret_cast<float4*>(y)[q] = o;
}

// ---------------------------------------------------------------------------
extern "C" void kernel_launch(void* const* d_in, const int* in_sizes, int n_in,
                              void* d_out, int out_size)
{
    // metadata order: x, attr_norm, levels, thr, parent, pixel_to_node
    const float* attr   = (const float*)d_in[1];
    const float* levels = (const float*)d_in[2];
    const float* thr    = (const float*)d_in[3];
    const int*   parent = (const int*)d_in[4];
    const int*   ptn    = (const int*)d_in[5];
    float*       y      = (float*)d_out;

    void *pA = nullptr, *pB = nullptr;
    cudaGetSymbolAddress(&pA, g_bufA);
    cudaGetSymbolAddress(&pB, g_bufB);
    int2* A = (int2*)pA;
    int2* B = (int2*)pB;

    const int TPB = 256;
    const int gbN = (TOTN + TPB - 1) / TPB;

    k_build<<<gbN, TPB>>>(attr, levels, thr, parent);
    k_double<<<gbN, TPB>>>(A, B);   // jump 2
    k_double<<<gbN, TPB>>>(B, A);   // jump 4
    k_double<<<gbN, TPB>>>(A, B);   // jump 8
    k_climb<<<gbN, TPB>>>(B);

    const int gbP = (TOTP / 4 + TPB - 1) / TPB;
    k_gather<<<gbP, TPB>>>(ptn, y);
}